// round 1
// baseline (speedup 1.0000x reference)
#include <cuda_runtime.h>

// Problem constants
#define NB     2
#define LSEQ   1024
#define EMB    1024
#define HD     1024
#define MROWS  2048      // NB*LSEQ
#define HEADS  16
#define HHD    64
#define DEPTH  6

// Scratch buffers (no cudaMalloc allowed)
__device__ float g_x[MROWS * HD];
__device__ float g_q[MROWS * HD];
__device__ float g_k[MROWS * HD];
__device__ float g_v[MROWS * HD];
__device__ float g_diag[NB * HEADS * LSEQ];

// ---------------------------------------------------------------------------
// Embedding: x[n,l,:] = tok_emb[X[n,l],:] + pos_emb[l,:]
// ---------------------------------------------------------------------------
__global__ __launch_bounds__(256) void embed_kernel(
    const int* __restrict__ X, const float* __restrict__ tok,
    const float* __restrict__ pos, float* __restrict__ out)
{
    int row = blockIdx.x;            // 0..2047
    int l   = row & (LSEQ - 1);
    int t   = X[row];
    const float4* tp = (const float4*)(tok + (size_t)t * EMB);
    const float4* pp = (const float4*)(pos + (size_t)l * EMB);
    float4*       op = (float4*)(out + (size_t)row * EMB);
    int i = threadIdx.x;             // 256 threads * float4 = 1024
    float4 a = tp[i], b = pp[i];
    op[i] = make_float4(a.x + b.x, a.y + b.y, a.z + b.z, a.w + b.w);
}

// ---------------------------------------------------------------------------
// SGEMM: C(M=2048 x N=1024) = (A(2048x1024) @ W(1024x1024) + bias) * scale
//        [+ Res]        128x128 tile, BK=8, 256 threads, 8x8 per thread
// ---------------------------------------------------------------------------
template <bool HAS_RES>
__global__ __launch_bounds__(256) void sgemm_kernel(
    const float* __restrict__ A, const float* __restrict__ W,
    const float* __restrict__ bias, const float* __restrict__ Res,
    float* __restrict__ C, float scale)
{
    __shared__ float As[8][128];
    __shared__ float Bs[8][128];

    const int bm  = blockIdx.y << 7;
    const int bn  = blockIdx.x << 7;
    const int tid = threadIdx.x;

    const int arow = tid >> 1;          // 0..127
    const int acol = (tid & 1) << 2;    // 0 or 4
    const int brow = tid >> 5;          // 0..7
    const int bcol = (tid & 31) << 2;   // 0..124
    const int tx   = tid & 15;
    const int ty   = tid >> 4;

    const float* Ap = A + (size_t)(bm + arow) * 1024 + acol;
    const float* Wp = W + (size_t)brow * 1024 + bn + bcol;

    float acc[8][8];
#pragma unroll
    for (int i = 0; i < 8; i++)
#pragma unroll
        for (int j = 0; j < 8; j++) acc[i][j] = 0.0f;

    for (int k0 = 0; k0 < 1024; k0 += 8) {
        float4 av = *(const float4*)(Ap + k0);
        float4 wv = *(const float4*)(Wp + (size_t)k0 * 1024);
        As[acol + 0][arow] = av.x;
        As[acol + 1][arow] = av.y;
        As[acol + 2][arow] = av.z;
        As[acol + 3][arow] = av.w;
        *(float4*)&Bs[brow][bcol] = wv;
        __syncthreads();
#pragma unroll
        for (int kk = 0; kk < 8; kk++) {
            float af[8], bf[8];
            *(float4*)(af)     = *(const float4*)&As[kk][ty << 3];
            *(float4*)(af + 4) = *(const float4*)&As[kk][(ty << 3) + 4];
            *(float4*)(bf)     = *(const float4*)&Bs[kk][tx << 3];
            *(float4*)(bf + 4) = *(const float4*)&Bs[kk][(tx << 3) + 4];
#pragma unroll
            for (int i = 0; i < 8; i++)
#pragma unroll
                for (int j = 0; j < 8; j++)
                    acc[i][j] = fmaf(af[i], bf[j], acc[i][j]);
        }
        __syncthreads();
    }

    // Epilogue: (acc + bias) * scale  [+ Res]
    const int ncol = bn + (tx << 3);
    float bv[8];
    *(float4*)(bv)     = *(const float4*)(bias + ncol);
    *(float4*)(bv + 4) = *(const float4*)(bias + ncol + 4);
#pragma unroll
    for (int i = 0; i < 8; i++) {
        int m = bm + (ty << 3) + i;
        float* cp = C + (size_t)m * 1024 + ncol;
        float o[8];
#pragma unroll
        for (int j = 0; j < 8; j++) o[j] = (acc[i][j] + bv[j]) * scale;
        if (HAS_RES) {
            const float* rp = Res + (size_t)m * 1024 + ncol;
            float r[8];
            *(float4*)(r)     = *(const float4*)rp;
            *(float4*)(r + 4) = *(const float4*)(rp + 4);
#pragma unroll
            for (int j = 0; j < 8; j++) o[j] += r[j];
        }
        *(float4*)cp       = *(const float4*)(o);
        *(float4*)(cp + 4) = *(const float4*)(o + 4);
    }
}

// ---------------------------------------------------------------------------
// Attention diagonal:
//   per (n,e) block (contiguous 1024x64 slabs of Q,K):
//   diag[b] = exp(q_b . k_b) / sum_a exp(q_a . k_b)
// grid: (8 b-tiles of 128, 32 (n*HEADS+e)), 256 threads
// ---------------------------------------------------------------------------
__global__ __launch_bounds__(256) void attn_diag_kernel(
    const float* __restrict__ Q, const float* __restrict__ Kp,
    float* __restrict__ diag)
{
    __shared__ float Kst[64][128];   // [x][b]   32 KB
    __shared__ float Qst[64][32];    // [x][a]    8 KB
    __shared__ float red[8][128];    //           4 KB
    __shared__ float dnum[128];      //         0.5 KB

    const int he  = blockIdx.y;      // 0..31
    const int bt  = blockIdx.x;      // 0..7
    const int tid = threadIdx.x;
    const int tx  = tid & 15;
    const int ty  = tid >> 4;

    const float* Qb = Q  + (size_t)he * (LSEQ * HHD);
    const float* Kb = Kp + (size_t)he * (LSEQ * HHD) + (size_t)bt * 128 * HHD;

    // Load K tile 128 rows x 64 cols, transposed into Kst[x][b]
    for (int q4 = tid; q4 < 2048; q4 += 256) {
        int b  = q4 >> 4;
        int x4 = (q4 & 15) << 2;
        float4 v = *(const float4*)(Kb + (size_t)b * HHD + x4);
        Kst[x4 + 0][b] = v.x; Kst[x4 + 1][b] = v.y;
        Kst[x4 + 2][b] = v.z; Kst[x4 + 3][b] = v.w;
    }

    float csum[8];
#pragma unroll
    for (int j = 0; j < 8; j++) csum[j] = 0.0f;

    const int gb0 = bt * 128 + (tx << 3);

    for (int at = 0; at < 32; at++) {
        int a0 = at << 5;            // 32-row a-tile
        __syncthreads();             // protect Qst reuse
        for (int q4 = tid; q4 < 512; q4 += 256) {
            int a  = q4 >> 4;
            int x4 = (q4 & 15) << 2;
            float4 v = *(const float4*)(Qb + (size_t)(a0 + a) * HHD + x4);
            Qst[x4 + 0][a] = v.x; Qst[x4 + 1][a] = v.y;
            Qst[x4 + 2][a] = v.z; Qst[x4 + 3][a] = v.w;
        }
        __syncthreads();

        float s[2][8];
#pragma unroll
        for (int i = 0; i < 2; i++)
#pragma unroll
            for (int j = 0; j < 8; j++) s[i][j] = 0.0f;

#pragma unroll 16
        for (int x = 0; x < 64; x++) {
            float2 qv = *(const float2*)&Qst[x][ty << 1];
            float4 k0 = *(const float4*)&Kst[x][tx << 3];
            float4 k1 = *(const float4*)&Kst[x][(tx << 3) + 4];
            s[0][0] = fmaf(qv.x, k0.x, s[0][0]);
            s[0][1] = fmaf(qv.x, k0.y, s[0][1]);
            s[0][2] = fmaf(qv.x, k0.z, s[0][2]);
            s[0][3] = fmaf(qv.x, k0.w, s[0][3]);
            s[0][4] = fmaf(qv.x, k1.x, s[0][4]);
            s[0][5] = fmaf(qv.x, k1.y, s[0][5]);
            s[0][6] = fmaf(qv.x, k1.z, s[0][6]);
            s[0][7] = fmaf(qv.x, k1.w, s[0][7]);
            s[1][0] = fmaf(qv.y, k0.x, s[1][0]);
            s[1][1] = fmaf(qv.y, k0.y, s[1][1]);
            s[1][2] = fmaf(qv.y, k0.z, s[1][2]);
            s[1][3] = fmaf(qv.y, k0.w, s[1][3]);
            s[1][4] = fmaf(qv.y, k1.x, s[1][4]);
            s[1][5] = fmaf(qv.y, k1.y, s[1][5]);
            s[1][6] = fmaf(qv.y, k1.z, s[1][6]);
            s[1][7] = fmaf(qv.y, k1.w, s[1][7]);
        }

#pragma unroll
        for (int i = 0; i < 2; i++) {
            int ga = a0 + (ty << 1) + i;
#pragma unroll
            for (int j = 0; j < 8; j++) {
                float e = __expf(s[i][j]);
                csum[j] += e;
                if (ga == gb0 + j) dnum[(tx << 3) + j] = e;  // diagonal hit
            }
        }
    }

    // Reduce csum over ty (16 partials per column b)
#pragma unroll
    for (int j = 0; j < 8; j++)
        csum[j] += __shfl_down_sync(0xffffffffu, csum[j], 16);
    __syncthreads();                 // dnum writes done; prep red
    if ((ty & 1) == 0) {
        int w = ty >> 1;             // warp index 0..7
#pragma unroll
        for (int j = 0; j < 8; j++) red[w][(tx << 3) + j] = csum[j];
    }
    __syncthreads();
    if (tid < 128) {
        float d = 0.0f;
#pragma unroll
        for (int w = 0; w < 8; w++) d += red[w][tid];
        diag[(size_t)he * LSEQ + bt * 128 + tid] = dnum[tid] / d;
    }
}

// ---------------------------------------------------------------------------
// U = diag * V (broadcast over HH), on the flat (N,L,H) buffer
// ---------------------------------------------------------------------------
__global__ __launch_bounds__(256) void scalev_kernel(
    const float* __restrict__ V, const float* __restrict__ diag,
    float* __restrict__ U)
{
    int g  = blockIdx.x * 256 + threadIdx.x;   // float4 index, 524288 total
    int he = g >> 14;                          // 16384 float4 per (n,e) block
    int l2 = (g >> 4) & 1023;                  // 16 float4 per row of HH=64
    float d = diag[(size_t)he * LSEQ + l2];
    float4 v = ((const float4*)V)[g];
    ((float4*)U)[g] = make_float4(v.x * d, v.y * d, v.z * d, v.w * d);
}

// ---------------------------------------------------------------------------
// LayerNorm over last dim (1024), biased variance, eps=1e-5
// ---------------------------------------------------------------------------
__global__ __launch_bounds__(256) void ln_kernel(
    const float* __restrict__ T, const float* __restrict__ g,
    const float* __restrict__ b, float* __restrict__ O)
{
    __shared__ float rs[8], rs2[8];
    int row = blockIdx.x;
    int tid = threadIdx.x;
    const float4* in = (const float4*)(T + (size_t)row * HD);
    float4 v = in[tid];
    float s  = v.x + v.y + v.z + v.w;
    float s2 = v.x * v.x + v.y * v.y + v.z * v.z + v.w * v.w;
#pragma unroll
    for (int o = 16; o > 0; o >>= 1) {
        s  += __shfl_down_sync(0xffffffffu, s,  o);
        s2 += __shfl_down_sync(0xffffffffu, s2, o);
    }
    if ((tid & 31) == 0) { rs[tid >> 5] = s; rs2[tid >> 5] = s2; }
    __syncthreads();
    float ts = 0.0f, ts2 = 0.0f;
#pragma unroll
    for (int w = 0; w < 8; w++) { ts += rs[w]; ts2 += rs2[w]; }
    float mean = ts * (1.0f / HD);
    float var  = ts2 * (1.0f / HD) - mean * mean;
    float rstd = rsqrtf(var + 1e-5f);
    float4 gv = ((const float4*)g)[tid];
    float4 bv = ((const float4*)b)[tid];
    float4 o;
    o.x = (v.x - mean) * rstd * gv.x + bv.x;
    o.y = (v.y - mean) * rstd * gv.y + bv.y;
    o.z = (v.z - mean) * rstd * gv.z + bv.z;
    o.w = (v.w - mean) * rstd * gv.w + bv.w;
    ((float4*)(O + (size_t)row * HD))[tid] = o;
}

// ---------------------------------------------------------------------------
// Launch
// ---------------------------------------------------------------------------
extern "C" void kernel_launch(void* const* d_in, const int* in_sizes, int n_in,
                              void* d_out, int out_size)
{
    const int*   X   = (const int*)d_in[0];
    const float* tok = (const float*)d_in[1];
    const float* pos = (const float*)d_in[2];
    const float* Wq  = (const float*)d_in[3];
    const float* bq  = (const float*)d_in[4];
    const float* Wk  = (const float*)d_in[5];
    const float* bk  = (const float*)d_in[6];
    const float* Wv  = (const float*)d_in[7];
    const float* bv  = (const float*)d_in[8];
    const float* Wo  = (const float*)d_in[9];
    const float* bo  = (const float*)d_in[10];
    const float* Wff = (const float*)d_in[11];
    const float* bff = (const float*)d_in[12];
    const float* g1  = (const float*)d_in[13];
    const float* b1  = (const float*)d_in[14];

    float *px, *pq, *pk, *pv, *pd;
    cudaGetSymbolAddress((void**)&px, g_x);
    cudaGetSymbolAddress((void**)&pq, g_q);
    cudaGetSymbolAddress((void**)&pk, g_k);
    cudaGetSymbolAddress((void**)&pv, g_v);
    cudaGetSymbolAddress((void**)&pd, g_diag);

    embed_kernel<<<MROWS, 256>>>(X, tok, pos, px);

    const dim3 ggrid(8, 16);          // N tiles x M tiles (128x128)
    const float inv_sqrt_h = 0.03125f;  // 1/sqrt(1024)

    for (int lyr = 0; lyr < DEPTH; lyr++) {
        const size_t wOff = (size_t)lyr * 1024 * 1024;
        const size_t bOff = (size_t)lyr * 1024;

        // Q, K (scaled), V
        sgemm_kernel<false><<<ggrid, 256>>>(px, Wq + wOff, bq + bOff, nullptr, pq, inv_sqrt_h);
        sgemm_kernel<false><<<ggrid, 256>>>(px, Wk + wOff, bk + bOff, nullptr, pk, inv_sqrt_h);
        sgemm_kernel<false><<<ggrid, 256>>>(px, Wv + wOff, bv + bOff, nullptr, pv, 1.0f);

        // diagonal of query-axis softmax
        attn_diag_kernel<<<dim3(8, 32), 256>>>(pq, pk, pd);

        // U = diag * V  (into pq)
        scalev_kernel<<<2048, 256>>>(pv, pd, pq);

        // t = U @ Wo + bo + x   (into pk)
        sgemm_kernel<true><<<ggrid, 256>>>(pq, Wo + wOff, bo + bOff, px, pk, 1.0f);

        // h = LayerNorm(t)      (into pv)
        ln_kernel<<<MROWS, 256>>>(pk, g1 + bOff, b1 + bOff, pv);

        // y = h @ Wff + bff + h (into x for next layer, or d_out)
        float* yout = (lyr == DEPTH - 1) ? (float*)d_out : px;
        sgemm_kernel<true><<<ggrid, 256>>>(pv, Wff + wOff, bff + bOff, pv, yout, 1.0f);
    }
}